// round 15
// baseline (speedup 1.0000x reference)
#include <cuda_runtime.h>
#include <cuda_bf16.h>
#include <math.h>

#define BATCH   128
#define OUT_DIM 1024
#define IN_DIM  2048
#define QCAP    24          // per quarter-row cap: P(Poisson(2)>24) ~ 1e-17
#define QPAD    4           // unconditional gathers per quarter (P(>4)=5.3% -> tail)
#define GRID    512
#define THREADS 256
#define NGROUP  32          // level-1 counters (distinct L2 lines)
#define GSIZE   (GRID / NGROUP)   // 16 arrivals per lvl1 counter

// Scratch (no allocations anywhere): transposed x + sentinel row = 1.0f
__device__ float g_xT[(IN_DIM + 1) * BATCH];
__device__ unsigned long long g_lvl1[NGROUP * 16];  // 128B-strided (16 ull apart)
__device__ unsigned long long g_root;               // 32 adds per launch

__device__ __forceinline__ unsigned long long atom_add_acqrel(
        unsigned long long* p, unsigned long long v) {
    unsigned long long old;
    asm volatile("atom.acq_rel.gpu.global.add.u64 %0, [%1], %2;"
                 : "=l"(old) : "l"(p), "l"(v) : "memory");
    return old;
}
__device__ __forceinline__ unsigned long long ld_acquire(
        const unsigned long long* p) {
    unsigned long long v;
    asm volatile("ld.acquire.gpu.global.u64 %0, [%1];"
                 : "=l"(v) : "l"(p) : "memory");
    return v;
}

// ---------------------------------------------------------------------------
// ONE kernel, one wave. Block = 2 check rows x 128 batches + one 16x32
// transpose tile of x. Tree barrier: <=16 RMWs per L2 address (parallel
// across 32 lines) + 32 root RMWs, instead of 512 serialized on one line.
// ---------------------------------------------------------------------------
__global__ void __launch_bounds__(THREADS, 4)
bp_fused4(const float* __restrict__ mask, const float* __restrict__ x,
          float* __restrict__ out) {
    __shared__ float          s_tile[16][33];
    __shared__ unsigned short s_idx[2][4][QCAP];
    __shared__ int            s_cnt[2][4];
    __shared__ float          s_out[2][BATCH];
    __shared__ unsigned long long s_tgt;

    const int tid  = threadIdx.x;
    const int lane = tid & 31;
    const int w    = tid >> 5;                    // 0..7
    const int r    = w >> 2;                      // row within block
    const int q    = w & 3;                       // quarter (A) / batch-quarter (B)
    const int o0   = blockIdx.x * 2;
    const int o    = o0 + r;

    // ---- ① transpose tile loads FIRST (they gate the chip-wide barrier) ----
    const int rt = blockIdx.x >> 6;               // 0..7   batch tile
    const int ct = blockIdx.x & 63;               // 0..63  col tile
    const int tb = tid >> 4;                      // 0..15  batch within tile
    const int tc = (tid & 15) * 2;                // 0..30  col pair
    float2 tv = *reinterpret_cast<const float2*>(
        x + (size_t)(rt * 16 + tb) * IN_DIM + ct * 32 + tc);

    // ---- ② mask loads: quarter q of row o (4 x LDG.128, in flight) ----
    const uint4* rp = reinterpret_cast<const uint4*>(
        mask + (size_t)o * IN_DIM + q * (IN_DIM / 4));
    uint4 v[4];
    #pragma unroll
    for (int u = 0; u < 4; u++)
        v[u] = rp[u * 32 + lane];

    // ---- ③ finish transpose: stage, flip, store coalesced ----
    s_tile[tb][tc]     = tv.x;
    s_tile[tb][tc + 1] = tv.y;
    __syncthreads();
    {
        const int c  = tid >> 3;                  // 0..31
        const int b2 = (tid & 7) * 2;             // 0..14
        float2 wv = make_float2(s_tile[b2][c], s_tile[b2 + 1][c]);
        *reinterpret_cast<float2*>(
            &g_xT[(size_t)(ct * 32 + c) * BATCH + rt * 16 + b2]) = wv;
        if (blockIdx.x == 0 && tid < BATCH)       // sentinel row -> 1.0f
            g_xT[(size_t)IN_DIM * BATCH + tid] = 1.0f;
    }
    __syncthreads();

    // ---- ④ TREE ARRIVE: lvl1 (<=16 RMWs/line, 32 lines) -> root (32 RMWs) ----
    if (tid == 0) {
        unsigned long long* myc = &g_lvl1[(blockIdx.x >> 4) * 16];
        unsigned long long old = atom_add_acqrel(myc, 1ULL);   // release my stores
        unsigned long long gen = old / GSIZE;
        if ((old % GSIZE) == (GSIZE - 1))          // last of group this generation
            atom_add_acqrel(&g_root, 1ULL);        // carries group's history
        s_tgt = (gen + 1ULL) * NGROUP;
    }

    // ---- ⑤ block-local extraction (overlaps peers' arrivals) ----
    {
        unsigned m = 0;                           // values die into bits
        #pragma unroll
        for (int u = 0; u < 4; u++) {
            unsigned bits = (unsigned)(v[u].x != 0u)
                          | ((unsigned)(v[u].y != 0u) << 1)
                          | ((unsigned)(v[u].z != 0u) << 2)
                          | ((unsigned)(v[u].w != 0u) << 3);
            m |= bits << (u * 4);
        }

        int mycnt = __popc(m);
        int scan  = mycnt;                        // inclusive warp scan
        #pragma unroll
        for (int d = 1; d < 32; d <<= 1) {
            int t = __shfl_up_sync(0xffffffffu, scan, d);
            if (lane >= d) scan += t;
        }
        const int total = __shfl_sync(0xffffffffu, scan, 31);
        int pos = scan - mycnt;                   // exclusive prefix (order-free)

        const int cbase = q * (IN_DIM / 4) + 4 * lane;
        while (m) {                               // scatter set bits -> shared
            int bit = __ffs(m) - 1;
            m &= m - 1;
            int col = cbase + 128 * (bit >> 2) + (bit & 3);
            if (pos < QCAP)
                s_idx[r][q][pos] = (unsigned short)col;
            pos++;
        }
        for (int j = total + lane; j < QPAD; j += 32)  // sentinel pad
            s_idx[r][q][j] = (unsigned short)IN_DIM;
        if (lane == 0)
            s_cnt[r][q] = total < QCAP ? total : QCAP;
    }
    __syncthreads();                              // s_idx ready + s_tgt visible

    // ---- ⑥ WAIT: acquire-poll the root (reads only; no RMW convoy) ----
    if (tid == 0) {
        const unsigned long long tgt = s_tgt;
        while (ld_acquire(&g_root) < tgt)
            __nanosleep(32);
    }
    __syncthreads();

    // ---- ⑦ phase B: warp (r, q) -> batches [32q, 32q+32) of row r ----
    {
        const int b = q * 32 + lane;              // one batch per lane

        int cols[4 * QPAD];
        #pragma unroll
        for (int qq = 0; qq < 4; qq++)            // warp-uniform LDS broadcast
            #pragma unroll
            for (int k = 0; k < QPAD; k++)
                cols[qq * QPAD + k] = s_idx[r][qq][k];

        float g[4 * QPAD];
        #pragma unroll
        for (int k = 0; k < 4 * QPAD; k++)        // 16 coalesced 128B gathers
            g[k] = g_xT[(size_t)cols[k] * BATCH + b];

        float p = (((g[0]  * g[1])  * (g[2]  * g[3])) *
                   ((g[4]  * g[5])  * (g[6]  * g[7]))) *
                  (((g[8]  * g[9])  * (g[10] * g[11])) *
                   ((g[12] * g[13]) * (g[14] * g[15])));

        #pragma unroll
        for (int qq = 0; qq < 4; qq++) {          // warp-uniform tails (~5%/quarter)
            const int n = s_cnt[r][qq];
            #pragma unroll 1
            for (int j = QPAD; j < n; j++)
                p *= g_xT[(size_t)s_idx[r][qq][j] * BATCH + b];
        }

        const float lim = 1.0f - 1e-7f;           // folds to 0.99999988f
        p = fminf(fmaxf(p, -lim), lim);
        s_out[r][b] = __logf(__fdividef(1.0f + p, 1.0f - p));
    }
    __syncthreads();

    // ---- stores: thread t<128 -> batch t, float2 out[t][o0..o0+1] ----
    if (tid < BATCH) {
        float2 a = make_float2(s_out[0][tid], s_out[1][tid]);
        *reinterpret_cast<float2*>(out + (size_t)tid * OUT_DIM + o0) = a;
    }
}

// ---------------------------------------------------------------------------
extern "C" void kernel_launch(void* const* d_in, const int* in_sizes, int n_in,
                              void* d_out, int out_size) {
    const float* x    = (const float*)d_in[0];   // [128, 2048]
    const float* mask = (const float*)d_in[1];   // [1024, 2048]
    float*       out  = (float*)d_out;           // [128, 1024]

    bp_fused4<<<GRID, THREADS>>>(mask, x, out);  // ONE launch, one wave
}

// round 16
// speedup vs baseline: 1.0621x; 1.0621x over previous
#include <cuda_runtime.h>
#include <cuda_bf16.h>
#include <math.h>

#define BATCH   128
#define OUT_DIM 1024
#define IN_DIM  2048
#define QCAP    24          // per quarter-row cap: P(Poisson(2)>24) ~ 1e-17
#define QPAD    4           // unconditional gathers per quarter (P(>4)=5.3% -> tail)
#define GRID    512
#define THREADS 256

// Scratch (no allocations anywhere): transposed x + sentinel row = 1.0f
__device__ float g_xT[(IN_DIM + 1) * BATCH];
__device__ unsigned long long g_bar;    // monotonic arrivals (replay-safe)

__device__ __forceinline__ unsigned long long ld_acquire(
        const unsigned long long* p) {
    unsigned long long v;
    asm volatile("ld.acquire.gpu.global.u64 %0, [%1];"
                 : "=l"(v) : "l"(p) : "memory");
    return v;
}

// ---------------------------------------------------------------------------
// ONE kernel, one wave (512 x 256). Block = 2 check rows x 128 batches + one
// 16x32 transpose tile of x. Simple release/acquire barrier (R14 — fastest).
// Post-barrier chain minimized: gather addresses prefetched into registers
// BEFORE the wait, so the synchronized tail is gather -> product -> log only.
// ---------------------------------------------------------------------------
__global__ void __launch_bounds__(THREADS, 4)
bp_fused5(const float* __restrict__ mask, const float* __restrict__ x,
          float* __restrict__ out) {
    __shared__ float          s_tile[16][33];
    __shared__ unsigned short s_idx[2][4][QCAP];
    __shared__ int            s_cnt[2][4];
    __shared__ float          s_out[2][BATCH];
    __shared__ unsigned long long s_tgt;

    const int tid  = threadIdx.x;
    const int lane = tid & 31;
    const int w    = tid >> 5;                    // 0..7
    const int r    = w >> 2;                      // row within block
    const int q    = w & 3;                       // quarter (A) / batch-quarter (B)
    const int o0   = blockIdx.x * 2;
    const int o    = o0 + r;

    // ---- ① transpose tile loads FIRST (they gate the chip-wide barrier) ----
    const int rt = blockIdx.x >> 6;               // 0..7   batch tile
    const int ct = blockIdx.x & 63;               // 0..63  col tile
    const int tb = tid >> 4;                      // 0..15  batch within tile
    const int tc = (tid & 15) * 2;                // 0..30  col pair
    float2 tv = *reinterpret_cast<const float2*>(
        x + (size_t)(rt * 16 + tb) * IN_DIM + ct * 32 + tc);

    // ---- ② mask loads: quarter q of row o (4 x LDG.128, in flight) ----
    const uint4* rp = reinterpret_cast<const uint4*>(
        mask + (size_t)o * IN_DIM + q * (IN_DIM / 4));
    uint4 v[4];
    #pragma unroll
    for (int u = 0; u < 4; u++)
        v[u] = rp[u * 32 + lane];

    // ---- ③ finish transpose: stage, flip, store coalesced ----
    s_tile[tb][tc]     = tv.x;
    s_tile[tb][tc + 1] = tv.y;
    __syncthreads();
    {
        const int c  = tid >> 3;                  // 0..31
        const int b2 = (tid & 7) * 2;             // 0..14
        float2 wv = make_float2(s_tile[b2][c], s_tile[b2 + 1][c]);
        *reinterpret_cast<float2*>(
            &g_xT[(size_t)(ct * 32 + c) * BATCH + rt * 16 + b2]) = wv;
        if (blockIdx.x < 4 && tid < 32)           // sentinel row, spread 4 ways
            g_xT[(size_t)IN_DIM * BATCH + blockIdx.x * 32 + tid] = 1.0f;
    }
    __syncthreads();

    // ---- ④ ARRIVE: release folded into the atomic (R14 barrier) ----
    if (tid == 0) {
        unsigned long long old;
        asm volatile("atom.release.gpu.global.add.u64 %0, [%1], %2;"
                     : "=l"(old) : "l"(&g_bar), "l"(1ULL) : "memory");
        s_tgt = (old / GRID + 1ULL) * GRID;
    }

    // ---- ⑤ block-local extraction (overlaps peers' transposes/arrivals) ----
    {
        unsigned m = 0;                           // values die into bits
        #pragma unroll
        for (int u = 0; u < 4; u++) {
            unsigned bits = (unsigned)(v[u].x != 0u)
                          | ((unsigned)(v[u].y != 0u) << 1)
                          | ((unsigned)(v[u].z != 0u) << 2)
                          | ((unsigned)(v[u].w != 0u) << 3);
            m |= bits << (u * 4);
        }

        int mycnt = __popc(m);
        int scan  = mycnt;                        // inclusive warp scan
        #pragma unroll
        for (int d = 1; d < 32; d <<= 1) {
            int t = __shfl_up_sync(0xffffffffu, scan, d);
            if (lane >= d) scan += t;
        }
        const int total = __shfl_sync(0xffffffffu, scan, 31);
        int pos = scan - mycnt;                   // exclusive prefix (order-free)

        const int cbase = q * (IN_DIM / 4) + 4 * lane;
        while (m) {                               // scatter set bits -> shared
            int bit = __ffs(m) - 1;
            m &= m - 1;
            int col = cbase + 128 * (bit >> 2) + (bit & 3);
            if (pos < QCAP)
                s_idx[r][q][pos] = (unsigned short)col;
            pos++;
        }
        for (int j = total + lane; j < QPAD; j += 32)  // sentinel pad
            s_idx[r][q][j] = (unsigned short)IN_DIM;
        if (lane == 0)
            s_cnt[r][q] = total < QCAP ? total : QCAP;
    }
    __syncthreads();                              // s_idx ready + s_tgt visible

    // ---- ⑥ PREFETCH gather addresses + counts into registers (pre-wait) ----
    int cols[4 * QPAD];
    int cnts[4];
    #pragma unroll
    for (int qq = 0; qq < 4; qq++) {              // warp-uniform LDS broadcast
        cnts[qq] = s_cnt[r][qq];
        #pragma unroll
        for (int k = 0; k < QPAD; k++)
            cols[qq * QPAD + k] = s_idx[r][qq][k];
    }

    // ---- ⑦ WAIT: acquire-poll (post-barrier chain is now minimal) ----
    if (tid == 0) {
        const unsigned long long tgt = s_tgt;
        while (ld_acquire(&g_bar) < tgt)
            __nanosleep(32);
    }
    __syncthreads();

    // ---- ⑧ phase B: warp (r, q) -> batches [32q, 32q+32) of row r ----
    {
        const int b = q * 32 + lane;              // one batch per lane

        float g[4 * QPAD];
        #pragma unroll
        for (int k = 0; k < 4 * QPAD; k++)        // 16 coalesced 128B gathers
            g[k] = g_xT[(size_t)cols[k] * BATCH + b];

        float p = (((g[0]  * g[1])  * (g[2]  * g[3])) *
                   ((g[4]  * g[5])  * (g[6]  * g[7]))) *
                  (((g[8]  * g[9])  * (g[10] * g[11])) *
                   ((g[12] * g[13]) * (g[14] * g[15])));

        #pragma unroll
        for (int qq = 0; qq < 4; qq++) {          // warp-uniform tails (~5%/quarter)
            const int n = cnts[qq];
            #pragma unroll 1
            for (int j = QPAD; j < n; j++)
                p *= g_xT[(size_t)s_idx[r][qq][j] * BATCH + b];
        }

        const float lim = 1.0f - 1e-7f;           // folds to 0.99999988f
        p = fminf(fmaxf(p, -lim), lim);
        s_out[r][b] = __logf(__fdividef(1.0f + p, 1.0f - p));
    }
    __syncthreads();

    // ---- stores: thread t<128 -> batch t, float2 out[t][o0..o0+1] ----
    if (tid < BATCH) {
        float2 a = make_float2(s_out[0][tid], s_out[1][tid]);
        *reinterpret_cast<float2*>(out + (size_t)tid * OUT_DIM + o0) = a;
    }
}

// ---------------------------------------------------------------------------
extern "C" void kernel_launch(void* const* d_in, const int* in_sizes, int n_in,
                              void* d_out, int out_size) {
    const float* x    = (const float*)d_in[0];   // [128, 2048]
    const float* mask = (const float*)d_in[1];   // [1024, 2048]
    float*       out  = (float*)d_out;           // [128, 1024]

    bp_fused5<<<GRID, THREADS>>>(mask, x, out);  // ONE launch, one wave
}